// round 1
// baseline (speedup 1.0000x reference)
#include <cuda_runtime.h>
#include <cstdint>

// GeometricEdgeConv fused kernel.
//
// Math reduction: mean_k(h_ij @ W_e) == (mean_k h_ij) @ W_e  (linear, no bias),
// so per point we build u[260] = [x_i (128) | mean_k x_j (128) | mean_k (p_i-p_j) (3) | mean_k |p_i-p_j|^2 (1)]
// and compute out = leaky_relu(u[0:128] @ W_self + u[128:260] @ W_edge).
//
// One warp handles one point. 8 warps per block.

namespace {

constexpr int Nn   = 16384;
constexpr int Cc   = 128;
constexpr int Kk   = 16;

__device__ __forceinline__ uint64_t pack2(float v) {
    uint64_t r;
    asm("mov.b64 %0, {%1, %1};" : "=l"(r) : "f"(v));
    return r;
}

__device__ __forceinline__ void fma2(uint64_t& acc, uint64_t w, uint64_t v) {
    asm("fma.rn.f32x2 %0, %1, %2, %0;" : "+l"(acc) : "l"(w), "l"(v));
}

__device__ __forceinline__ float2 unpack2(uint64_t v) {
    float2 f;
    asm("mov.b64 {%0, %1}, %2;" : "=f"(f.x), "=f"(f.y) : "l"(v));
    return f;
}

__global__ __launch_bounds__(256) void geconv_kernel(
    const float* __restrict__ x,    // [B, N, C]
    const float* __restrict__ pos,  // [B, N, 3]
    const int*   __restrict__ idx,  // [B, N, K]
    const float* __restrict__ ws,   // [C, OUT] = [128,128]
    const float* __restrict__ we,   // [C+4, OUT] = [132,128]
    float*       __restrict__ out)  // [B, N, OUT]
{
    __shared__ __align__(16) float u_sm[8][264];   // per-warp u[260] (+pad)

    const int warp = threadIdx.x >> 5;
    const int lane = threadIdx.x & 31;
    const int p    = (blockIdx.x << 3) + warp;     // global point id, 0..131071
    const int b    = p >> 14;                      // N = 16384
    const int n    = p & (Nn - 1);

    const float* xb = x + (size_t)b * Nn * Cc;
    float* u = u_sm[warp];

    // ---- load neighbor indices (lane k holds idx[p][k] for k<16) ----
    int my_idx = 0;
    if (lane < Kk) my_idx = __ldg(idx + (size_t)p * Kk + lane);

    // ---- self feature row into u[0:128] ----
    float4 xi = ((const float4*)(xb + (size_t)n * Cc))[lane];
    *(float4*)(u + 4 * lane) = xi;

    // ---- gathered neighbor-feature mean into u[128:256] ----
    float4 s = make_float4(0.f, 0.f, 0.f, 0.f);
    #pragma unroll
    for (int k = 0; k < Kk; ++k) {
        int j = __shfl_sync(0xffffffffu, my_idx, k);
        float4 v = ((const float4*)(xb + (size_t)j * Cc))[lane];
        s.x += v.x; s.y += v.y; s.z += v.z; s.w += v.w;
    }
    const float inv = 1.0f / 16.0f;
    float4 g = make_float4(s.x * inv, s.y * inv, s.z * inv, s.w * inv);
    *(float4*)(u + Cc + 4 * lane) = g;

    // ---- rel_pos / dist_sq means into u[256:260] ----
    float r0 = 0.f, r1 = 0.f, r2 = 0.f, ds = 0.f;
    {
        const float* pb = pos + (size_t)b * Nn * 3;
        if (lane < Kk) {
            float pi0 = pb[n * 3 + 0];
            float pi1 = pb[n * 3 + 1];
            float pi2 = pb[n * 3 + 2];
            const float* pj = pb + (size_t)my_idx * 3;
            r0 = pi0 - pj[0];
            r1 = pi1 - pj[1];
            r2 = pi2 - pj[2];
            ds = r0 * r0 + r1 * r1 + r2 * r2;
        }
    }
    #pragma unroll
    for (int o = 16; o >= 1; o >>= 1) {
        r0 += __shfl_xor_sync(0xffffffffu, r0, o);
        r1 += __shfl_xor_sync(0xffffffffu, r1, o);
        r2 += __shfl_xor_sync(0xffffffffu, r2, o);
        ds += __shfl_xor_sync(0xffffffffu, ds, o);
    }
    if (lane == 0) {
        u[256] = r0 * inv;
        u[257] = r1 * inv;
        u[258] = r2 * inv;
        u[259] = ds * inv;
    }
    __syncwarp();

    // ---- per-point GEMV: each lane computes outputs [4*lane, 4*lane+3] ----
    // Packed f32x2 FMAs: 2 independent accumulator chains (a01, a23).
    uint64_t a01 = 0, a23 = 0;
    const ulonglong2* __restrict__ wsv = (const ulonglong2*)ws;  // 32 per row
    const ulonglong2* __restrict__ wev = (const ulonglong2*)we;

    // self-weight part: rows 0..127 of u against ws
    #pragma unroll 4
    for (int eg = 0; eg < 32; ++eg) {
        float4 uv = *(const float4*)(u + 4 * eg);
        uint64_t v0 = pack2(uv.x), v1 = pack2(uv.y), v2 = pack2(uv.z), v3 = pack2(uv.w);
        ulonglong2 w0 = wsv[(4 * eg + 0) * 32 + lane];
        fma2(a01, w0.x, v0); fma2(a23, w0.y, v0);
        ulonglong2 w1 = wsv[(4 * eg + 1) * 32 + lane];
        fma2(a01, w1.x, v1); fma2(a23, w1.y, v1);
        ulonglong2 w2 = wsv[(4 * eg + 2) * 32 + lane];
        fma2(a01, w2.x, v2); fma2(a23, w2.y, v2);
        ulonglong2 w3 = wsv[(4 * eg + 3) * 32 + lane];
        fma2(a01, w3.x, v3); fma2(a23, w3.y, v3);
    }

    // edge-weight part: rows 0..131 of we against u[128..259]
    #pragma unroll 4
    for (int eg = 0; eg < 33; ++eg) {
        float4 uv = *(const float4*)(u + Cc + 4 * eg);
        uint64_t v0 = pack2(uv.x), v1 = pack2(uv.y), v2 = pack2(uv.z), v3 = pack2(uv.w);
        ulonglong2 w0 = wev[(4 * eg + 0) * 32 + lane];
        fma2(a01, w0.x, v0); fma2(a23, w0.y, v0);
        ulonglong2 w1 = wev[(4 * eg + 1) * 32 + lane];
        fma2(a01, w1.x, v1); fma2(a23, w1.y, v1);
        ulonglong2 w2 = wev[(4 * eg + 2) * 32 + lane];
        fma2(a01, w2.x, v2); fma2(a23, w2.y, v2);
        ulonglong2 w3 = wev[(4 * eg + 3) * 32 + lane];
        fma2(a01, w3.x, v3); fma2(a23, w3.y, v3);
    }

    // ---- epilogue: leaky_relu(0.2) + store ----
    float2 f01 = unpack2(a01);
    float2 f23 = unpack2(a23);
    float4 r;
    r.x = f01.x > 0.f ? f01.x : 0.2f * f01.x;
    r.y = f01.y > 0.f ? f01.y : 0.2f * f01.y;
    r.z = f23.x > 0.f ? f23.x : 0.2f * f23.x;
    r.w = f23.y > 0.f ? f23.y : 0.2f * f23.y;
    *(float4*)(out + (size_t)p * 128 + 4 * lane) = r;
}

}  // namespace

extern "C" void kernel_launch(void* const* d_in, const int* in_sizes, int n_in,
                              void* d_out, int out_size) {
    const float* x   = (const float*)d_in[0];   // [8,16384,128]
    const float* pos = (const float*)d_in[1];   // [8,16384,3]
    const int*   idx = (const int*)d_in[2];     // [8,16384,16]
    const float* ws  = (const float*)d_in[3];   // [128,128]
    const float* we  = (const float*)d_in[4];   // [132,128]
    float* out = (float*)d_out;                 // [8,16384,128]

    // 131072 points, 1 warp per point, 8 warps per block
    geconv_kernel<<<16384, 256>>>(x, pos, idx, ws, we, out);
}

// round 2
// speedup vs baseline: 2.3450x; 2.3450x over previous
#include <cuda_runtime.h>
#include <cstdint>

// GeometricEdgeConv fused, register-blocked.
//
// Math: mean_k(h @ We) == (mean_k h) @ We  (linear, no bias), so per point:
//   u[260] = [x_i | mean_k x_j | mean_k rel_pos | mean_k dist2]
//   out    = leaky_relu(u @ Wcat),  Wcat = [Ws ; We]  (260 x 128)
//
// Round-1 lesson: 1 warp/point streams all 133KB of weights through L1 per
// point -> L1 90% bound. Now each warp processes M=8 points (8x weight reuse)
// and weights are pre-packed in K-pairs so f32x2 FMAs accumulate even/odd K
// partial sums (no operand-duplication movs).

namespace {

constexpr int Nn = 16384;
constexpr int Cc = 128;
constexpr int Kk = 16;
constexpr int M  = 8;           // points per warp
constexpr int WARPS = 4;        // warps per block
constexpr int KP = 130;         // k-pairs (260 rows / 2)

// packed weights: wpack[kpair][col] = (w[2*kpair][col], w[2*kpair+1][col])
__device__ float2 g_wpack[KP * 128];

__global__ void geconv_prepack(const float* __restrict__ ws,
                               const float* __restrict__ we) {
    int tid = blockIdx.x * blockDim.x + threadIdx.x;   // 0..16639
    int r2 = tid >> 7;          // kpair
    int c  = tid & 127;
    int r  = 2 * r2;
    float f0 = (r     < 128) ? ws[r * 128 + c]       : we[(r - 128) * 128 + c];
    float f1 = (r + 1 < 128) ? ws[(r + 1) * 128 + c] : we[(r - 127) * 128 + c];
    g_wpack[tid] = make_float2(f0, f1);
}

__device__ __forceinline__ void fma2(uint64_t& acc, uint64_t w, uint64_t v) {
    asm("fma.rn.f32x2 %0, %1, %2, %0;" : "+l"(acc) : "l"(w), "l"(v));
}

__device__ __forceinline__ float2 unpack2(uint64_t v) {
    float2 f;
    asm("mov.b64 {%0, %1}, %2;" : "=f"(f.x), "=f"(f.y) : "l"(v));
    return f;
}

__global__ __launch_bounds__(128, 4) void geconv_kernel(
    const float* __restrict__ x,    // [B, N, C]
    const float* __restrict__ pos,  // [B, N, 3]
    const int*   __restrict__ idx,  // [B, N, K]
    float*       __restrict__ out)  // [B, N, 128]
{
    __shared__ __align__(16) float u_sm[WARPS * M][264];

    const int warp = threadIdx.x >> 5;
    const int lane = threadIdx.x & 31;
    const int base_p = blockIdx.x * (WARPS * M) + warp * M;  // first point of this warp
    const int b = base_p >> 14;                // blocks never straddle a batch (16384 % 32 == 0)
    const float* xb = x + (size_t)b * Nn * Cc;
    const float* pb = pos + (size_t)b * Nn * 3;
    const float inv = 1.0f / 16.0f;

    // ================= Phase 1: gather + average, build u rows =================
    #pragma unroll 1
    for (int m = 0; m < M; ++m) {
        const int p = base_p + m;
        const int n = p & (Nn - 1);
        float* u = u_sm[warp * M + m];

        int my_idx = 0;
        if (lane < Kk) my_idx = __ldg(idx + (size_t)p * Kk + lane);

        // self features -> u[0:128]
        float4 xi = ((const float4*)(xb + (size_t)n * Cc))[lane];
        *(float4*)(u + 4 * lane) = xi;

        // neighbor mean -> u[128:256]
        float4 s = make_float4(0.f, 0.f, 0.f, 0.f);
        #pragma unroll
        for (int k = 0; k < Kk; ++k) {
            int j = __shfl_sync(0xffffffffu, my_idx, k);
            float4 v = ((const float4*)(xb + (size_t)j * Cc))[lane];
            s.x += v.x; s.y += v.y; s.z += v.z; s.w += v.w;
        }
        *(float4*)(u + Cc + 4 * lane) =
            make_float4(s.x * inv, s.y * inv, s.z * inv, s.w * inv);

        // rel_pos / dist2 means -> u[256:260]
        float r0 = 0.f, r1 = 0.f, r2 = 0.f, ds = 0.f;
        if (lane < Kk) {
            float pi0 = pb[n * 3 + 0], pi1 = pb[n * 3 + 1], pi2 = pb[n * 3 + 2];
            const float* pj = pb + (size_t)my_idx * 3;
            r0 = pi0 - pj[0]; r1 = pi1 - pj[1]; r2 = pi2 - pj[2];
            ds = r0 * r0 + r1 * r1 + r2 * r2;
        }
        #pragma unroll
        for (int o = 16; o >= 1; o >>= 1) {
            r0 += __shfl_xor_sync(0xffffffffu, r0, o);
            r1 += __shfl_xor_sync(0xffffffffu, r1, o);
            r2 += __shfl_xor_sync(0xffffffffu, r2, o);
            ds += __shfl_xor_sync(0xffffffffu, ds, o);
        }
        if (lane == 0) {
            u[256] = r0 * inv; u[257] = r1 * inv;
            u[258] = r2 * inv; u[259] = ds * inv;
        }
    }
    __syncwarp();

    // ================= Phase 2: warp GEMM, 8 points x 4 cols per lane ==========
    // acc[m][c] is f32x2: .lo sums even-k rows, .hi sums odd-k rows.
    uint64_t acc[M][4];
    #pragma unroll
    for (int m = 0; m < M; ++m)
        #pragma unroll
        for (int c = 0; c < 4; ++c) acc[m][c] = 0;

    const ulonglong2* __restrict__ wp = (const ulonglong2*)g_wpack;  // 64 per kpair row
    const float* ubase = u_sm[warp * M];

    #pragma unroll 1
    for (int g = 0; g < 65; ++g) {              // 4 u-rows (= 2 kpairs) per iter
        const int kp0 = 2 * g;
        // weights: lane's cols 4*lane .. 4*lane+3 for both kpairs
        ulonglong2 wa0 = wp[kp0 * 64 + 2 * lane];        // kpair0, cols (4l, 4l+1)
        ulonglong2 wa1 = wp[kp0 * 64 + 2 * lane + 1];    // kpair0, cols (4l+2, 4l+3)
        ulonglong2 wb0 = wp[(kp0 + 1) * 64 + 2 * lane];
        ulonglong2 wb1 = wp[(kp0 + 1) * 64 + 2 * lane + 1];

        #pragma unroll
        for (int m = 0; m < M; ++m) {
            // u rows 4g..4g+3 for point m: (.x = rows 4g,4g+1) (.y = rows 4g+2,4g+3)
            ulonglong2 uv = *(const ulonglong2*)(ubase + (size_t)m * 264 + 4 * g);
            fma2(acc[m][0], wa0.x, uv.x);
            fma2(acc[m][1], wa0.y, uv.x);
            fma2(acc[m][2], wa1.x, uv.x);
            fma2(acc[m][3], wa1.y, uv.x);
            fma2(acc[m][0], wb0.x, uv.y);
            fma2(acc[m][1], wb0.y, uv.y);
            fma2(acc[m][2], wb1.x, uv.y);
            fma2(acc[m][3], wb1.y, uv.y);
        }
    }

    // ================= Epilogue: reduce pair, leaky_relu, store ================
    #pragma unroll
    for (int m = 0; m < M; ++m) {
        float4 r;
        float2 f0 = unpack2(acc[m][0]);
        float2 f1 = unpack2(acc[m][1]);
        float2 f2 = unpack2(acc[m][2]);
        float2 f3 = unpack2(acc[m][3]);
        float v0 = f0.x + f0.y;
        float v1 = f1.x + f1.y;
        float v2 = f2.x + f2.y;
        float v3 = f3.x + f3.y;
        r.x = v0 > 0.f ? v0 : 0.2f * v0;
        r.y = v1 > 0.f ? v1 : 0.2f * v1;
        r.z = v2 > 0.f ? v2 : 0.2f * v2;
        r.w = v3 > 0.f ? v3 : 0.2f * v3;
        *(float4*)(out + (size_t)(base_p + m) * 128 + 4 * lane) = r;
    }
}

}  // namespace

extern "C" void kernel_launch(void* const* d_in, const int* in_sizes, int n_in,
                              void* d_out, int out_size) {
    const float* x   = (const float*)d_in[0];   // [8,16384,128]
    const float* pos = (const float*)d_in[1];   // [8,16384,3]
    const int*   idx = (const int*)d_in[2];     // [8,16384,16]
    const float* ws  = (const float*)d_in[3];   // [128,128]
    const float* we  = (const float*)d_in[4];   // [132,128]
    float* out = (float*)d_out;                 // [8,16384,128]

    geconv_prepack<<<65, 256>>>(ws, we);        // 16640 threads, fills g_wpack
    geconv_kernel<<<131072 / (WARPS * M), WARPS * 32>>>(x, pos, idx, out);
}

// round 4
// speedup vs baseline: 2.5827x; 1.1014x over previous
#include <cuda_runtime.h>
#include <cuda_bf16.h>
#include <cstdint>

// GeometricEdgeConv: warp-specialized gather + mma.sync bf16-split GEMM.
// (tcgen05 is unavailable: harness compiles for plain sm_100 target.)
//
// u[260] = [x_i | mean_k x_j | mean_k rel_pos | mean_k dist2]  (K padded to 280)
// out    = leaky_relu(u @ Wcat), Wcat = [Ws; We] (260x128)
// bf16 hi/lo split, 3 products per K-chunk -> fp32-class accuracy.
//
// Persistent grid=148. Warps 4-7 gather tile i into buf(i&1) while warps 0-3
// run m16n8k16 HMMAs on tile i-1 from the other buffer. Weights W^T[n][k]
// (bf16 hi/lo) resident in smem; frags loaded with ldmatrix.

namespace {

constexpr int Nn = 16384, Cc = 128, Kk = 16;
constexpr int KPAD = 280;                 // k cols (560B rows: LDSM conflict-free)
constexpr int ROWB = KPAD * 2;            // 560 bytes per row
constexpr int TILE_M = 32;
constexpr int NTILES = 131072 / TILE_M;   // 4096
constexpr int WT_HALF = 128 * ROWB;       // 71680 bytes (hi); lo follows
constexpr int U_HALF  = TILE_M * ROWB;    // 17920 (hi); lo follows within buffer
constexpr int U_BUF   = 2 * U_HALF;       // 35840
constexpr int SM_WT   = 0;
constexpr int SM_U    = 2 * WT_HALF;      // 143360
constexpr int SM_TOTAL = SM_U + 2 * U_BUF;  // 215040

__device__ __nv_bfloat16 g_wt[2 * WT_HALF / 2];   // W^T hi[128][280] then lo

__device__ __forceinline__ uint32_t smem_u32(const void* p) {
    uint32_t a;
    asm("{ .reg .u64 t; cvta.to.shared.u64 t, %1; cvt.u32.u64 %0, t; }" : "=r"(a) : "l"(p));
    return a;
}
// pack two floats -> bf16x2 reg: lower half = a (first k), upper = b
__device__ __forceinline__ uint32_t cvt2bf(float a, float b) {
    uint32_t r;
    asm("cvt.rn.bf16x2.f32 %0, %1, %2;" : "=r"(r) : "f"(b), "f"(a));
    return r;
}
// residual of (a,b) against packed hi h
__device__ __forceinline__ uint32_t lo_pack(float a, float b, uint32_t h) {
    float la = a - __uint_as_float(h << 16);
    float lb = b - __uint_as_float(h & 0xffff0000u);
    return cvt2bf(la, lb);
}
__device__ __forceinline__ void sts64(uint32_t addr, uint32_t a, uint32_t b) {
    asm volatile("st.shared.v2.b32 [%0], {%1,%2};" :: "r"(addr), "r"(a), "r"(b) : "memory");
}
__device__ __forceinline__ void ldsm_x4(uint32_t addr, uint32_t* r) {
    asm volatile("ldmatrix.sync.aligned.m8n8.x4.shared.b16 {%0,%1,%2,%3}, [%4];"
                 : "=r"(r[0]), "=r"(r[1]), "=r"(r[2]), "=r"(r[3]) : "r"(addr));
}
__device__ __forceinline__ void mma_bf16(float* c, const uint32_t* a,
                                         uint32_t b0, uint32_t b1) {
    asm volatile(
        "mma.sync.aligned.m16n8k16.row.col.f32.bf16.bf16.f32 "
        "{%0,%1,%2,%3}, {%4,%5,%6,%7}, {%8,%9}, {%0,%1,%2,%3};"
        : "+f"(c[0]), "+f"(c[1]), "+f"(c[2]), "+f"(c[3])
        : "r"(a[0]), "r"(a[1]), "r"(a[2]), "r"(a[3]), "r"(b0), "r"(b1));
}

// ------------------------------------------------------------- weight prepack
__global__ void prepack(const float* __restrict__ ws, const float* __restrict__ we) {
    int t = blockIdx.x * blockDim.x + threadIdx.x;
    if (t >= 128 * KPAD) return;
    int n = t / KPAD, k = t % KPAD;
    float w = 0.f;
    if (k < 128) w = ws[k * 128 + n];
    else if (k < 260) w = we[(k - 128) * 128 + n];
    __nv_bfloat16 hi = __float2bfloat16_rn(w);
    __nv_bfloat16 lo = __float2bfloat16_rn(w - __bfloat162float(hi));
    g_wt[n * KPAD + k] = hi;
    g_wt[WT_HALF / 2 + n * KPAD + k] = lo;
}

// ------------------------------------------------------------------- main
__global__ __launch_bounds__(256, 1) void geconv(
    const float* __restrict__ x, const float* __restrict__ pos,
    const int* __restrict__ idx, float* __restrict__ out)
{
    extern __shared__ __align__(16) char smem[];
    const uint32_t smb = smem_u32(smem);
    const int tid = threadIdx.x, wid = tid >> 5, lane = tid & 31;

    // stage weights (hi+lo) into smem once
    {
        const int4* src = (const int4*)g_wt;
        int4* dst = (int4*)(smem + SM_WT);
        for (int i = tid; i < 2 * WT_HALF / 16; i += 256) dst[i] = src[i];
    }
    __syncthreads();

    const float inv = 1.0f / 16.0f;
    const int grid = gridDim.x;
    int n_t = (NTILES - (int)blockIdx.x + grid - 1) / grid;   // tiles for this CTA

    // per-thread ldmatrix offsets
    const int g8 = lane >> 3, r8 = lane & 7;
    const uint32_t a_off = (uint32_t)(((g8 & 1) * 8 + r8) * ROWB + (g8 >> 1) * 16);
    const uint32_t b_base = (uint32_t)(((g8 >> 1) * 8 + r8) * ROWB + (g8 & 1) * 16);

    for (int it = 0; it <= n_t; ++it) {
        if (wid >= 4) {
            // ======================= gather warps =======================
            if (it < n_t) {
                const int tile = blockIdx.x + it * grid;
                const int tile_p0 = tile * TILE_M;
                const int b = tile_p0 >> 14;
                const float* xb = x + (size_t)b * Nn * Cc;
                const float* pb = pos + (size_t)b * Nn * 3;
                const uint32_t ub = smb + SM_U + (uint32_t)(it & 1) * U_BUF;
                const int gw = wid - 4;

                #pragma unroll 1
                for (int j = 0; j < 8; ++j) {
                    const int m = gw * 8 + j;
                    const int p = tile_p0 + m;
                    const int n = p & (Nn - 1);
                    const uint32_t rb = ub + (uint32_t)m * ROWB;

                    int my_idx = 0;
                    if (lane < Kk) my_idx = __ldg(idx + (size_t)p * Kk + lane);

                    // self features -> k[4l..4l+3]
                    float4 xi = ((const float4*)(xb + (size_t)n * Cc))[lane];
                    uint32_t h0 = cvt2bf(xi.x, xi.y), h1 = cvt2bf(xi.z, xi.w);
                    sts64(rb + 8 * lane, h0, h1);
                    sts64(rb + U_HALF + 8 * lane,
                          lo_pack(xi.x, xi.y, h0), lo_pack(xi.z, xi.w, h1));

                    // neighbor mean -> k[128+4l ..]
                    float4 s = make_float4(0.f, 0.f, 0.f, 0.f);
                    #pragma unroll
                    for (int k = 0; k < Kk; ++k) {
                        int jj = __shfl_sync(0xffffffffu, my_idx, k);
                        float4 v = ((const float4*)(xb + (size_t)jj * Cc))[lane];
                        s.x += v.x; s.y += v.y; s.z += v.z; s.w += v.w;
                    }
                    s.x *= inv; s.y *= inv; s.z *= inv; s.w *= inv;
                    uint32_t g0 = cvt2bf(s.x, s.y), g1 = cvt2bf(s.z, s.w);
                    sts64(rb + 256 + 8 * lane, g0, g1);
                    sts64(rb + U_HALF + 256 + 8 * lane,
                          lo_pack(s.x, s.y, g0), lo_pack(s.z, s.w, g1));

                    // pos tail -> k[256..259], zeros k[260..279]
                    float r0 = 0.f, r1 = 0.f, r2 = 0.f, ds = 0.f;
                    if (lane < Kk) {
                        float pi0 = pb[n * 3], pi1 = pb[n * 3 + 1], pi2 = pb[n * 3 + 2];
                        const float* pj = pb + (size_t)my_idx * 3;
                        r0 = pi0 - pj[0]; r1 = pi1 - pj[1]; r2 = pi2 - pj[2];
                        ds = r0 * r0 + r1 * r1 + r2 * r2;
                    }
                    #pragma unroll
                    for (int o = 16; o >= 1; o >>= 1) {
                        r0 += __shfl_xor_sync(0xffffffffu, r0, o);
                        r1 += __shfl_xor_sync(0xffffffffu, r1, o);
                        r2 += __shfl_xor_sync(0xffffffffu, r2, o);
                        ds += __shfl_xor_sync(0xffffffffu, ds, o);
                    }
                    if (lane == 0) {
                        r0 *= inv; r1 *= inv; r2 *= inv; ds *= inv;
                        uint32_t t0 = cvt2bf(r0, r1), t1 = cvt2bf(r2, ds);
                        sts64(rb + 512, t0, t1);
                        sts64(rb + U_HALF + 512,
                              lo_pack(r0, r1, t0), lo_pack(r2, ds, t1));
                    } else if (lane <= 5) {
                        sts64(rb + 512 + 8 * lane, 0u, 0u);
                        sts64(rb + U_HALF + 512 + 8 * lane, 0u, 0u);
                    }
                }
            }
        } else {
            // ======================= mma warps =======================
            if (it >= 1) {
                const int tile = blockIdx.x + (it - 1) * grid;
                const uint32_t ub_hi = smb + SM_U + (uint32_t)((it - 1) & 1) * U_BUF;
                const uint32_t ub_lo = ub_hi + U_HALF;
                const uint32_t wt_hi = smb + SM_WT + (uint32_t)(32 * wid) * ROWB + b_base;
                const uint32_t wt_lo = wt_hi + WT_HALF;

                float c[2][4][4];
                #pragma unroll
                for (int mt = 0; mt < 2; ++mt)
                    #pragma unroll
                    for (int nt = 0; nt < 4; ++nt)
                        #pragma unroll
                        for (int q = 0; q < 4; ++q) c[mt][nt][q] = 0.f;

                #pragma unroll 1
                for (int kt = 0; kt < 17; ++kt) {
                    uint32_t bh0[4], bh1[4], bl0[4], bl1[4];
                    ldsm_x4(wt_hi + kt * 32, bh0);
                    ldsm_x4(wt_hi + kt * 32 + 16 * ROWB, bh1);
                    ldsm_x4(wt_lo + kt * 32, bl0);
                    ldsm_x4(wt_lo + kt * 32 + 16 * ROWB, bl1);
                    #pragma unroll
                    for (int mt = 0; mt < 2; ++mt) {
                        uint32_t ah[4], al[4];
                        ldsm_x4(ub_hi + (uint32_t)(mt * 16) * ROWB + kt * 32 + a_off, ah);
                        ldsm_x4(ub_lo + (uint32_t)(mt * 16) * ROWB + kt * 32 + a_off, al);
                        mma_bf16(c[mt][0], ah, bh0[0], bh0[1]);
                        mma_bf16(c[mt][1], ah, bh0[2], bh0[3]);
                        mma_bf16(c[mt][2], ah, bh1[0], bh1[1]);
                        mma_bf16(c[mt][3], ah, bh1[2], bh1[3]);
                        mma_bf16(c[mt][0], al, bh0[0], bh0[1]);
                        mma_bf16(c[mt][1], al, bh0[2], bh0[3]);
                        mma_bf16(c[mt][2], al, bh1[0], bh1[1]);
                        mma_bf16(c[mt][3], al, bh1[2], bh1[3]);
                        mma_bf16(c[mt][0], ah, bl0[0], bl0[1]);
                        mma_bf16(c[mt][1], ah, bl0[2], bl0[3]);
                        mma_bf16(c[mt][2], ah, bl1[0], bl1[1]);
                        mma_bf16(c[mt][3], ah, bl1[2], bl1[3]);
                    }
                }

                // epilogue: leaky_relu + store
                const int tile_p0 = tile * TILE_M;
                #pragma unroll
                for (int mt = 0; mt < 2; ++mt) {
                    #pragma unroll
                    for (int nt = 0; nt < 4; ++nt) {
                        const int m0 = mt * 16 + (lane >> 2);
                        const int nc = 32 * wid + nt * 8 + 2 * (lane & 3);
                        float* o0 = out + (size_t)(tile_p0 + m0) * 128 + nc;
                        float* o1 = out + (size_t)(tile_p0 + m0 + 8) * 128 + nc;
                        float v0 = c[mt][nt][0], v1 = c[mt][nt][1];
                        float v2 = c[mt][nt][2], v3 = c[mt][nt][3];
                        float2 w0, w1;
                        w0.x = v0 > 0.f ? v0 : 0.2f * v0;
                        w0.y = v1 > 0.f ? v1 : 0.2f * v1;
                        w1.x = v2 > 0.f ? v2 : 0.2f * v2;
                        w1.y = v3 > 0.f ? v3 : 0.2f * v3;
                        *(float2*)o0 = w0;
                        *(float2*)o1 = w1;
                    }
                }
            }
        }
        __syncthreads();
    }
}

}  // namespace

extern "C" void kernel_launch(void* const* d_in, const int* in_sizes, int n_in,
                              void* d_out, int out_size) {
    const float* x   = (const float*)d_in[0];   // [8,16384,128]
    const float* pos = (const float*)d_in[1];   // [8,16384,3]
    const int*   idx = (const int*)d_in[2];     // [8,16384,16]
    const float* ws  = (const float*)d_in[3];   // [128,128]
    const float* we  = (const float*)d_in[4];   // [132,128]
    float* out = (float*)d_out;

    cudaFuncSetAttribute(geconv, cudaFuncAttributeMaxDynamicSharedMemorySize, SM_TOTAL);
    prepack<<<140, 256>>>(ws, we);
    geconv<<<148, 256, SM_TOTAL>>>(x, pos, idx, out);
}

// round 5
// speedup vs baseline: 3.7289x; 1.4438x over previous
#include <cuda_runtime.h>
#include <cuda_bf16.h>
#include <cstdint>

// GeometricEdgeConv: warp-specialized gather + mma.sync bf16-split GEMM. v2.
// 512 threads: 8 mma warps (16 cols each) + 8 gather warps (4 points each,
// all 4 points' neighbor loads interleaved in one k-loop for MLP).
//
// u[260] = [x_i | mean_k x_j | mean_k rel_pos | mean_k dist2]  (K padded 280)
// out = leaky_relu(u @ [Ws; We]); bf16 hi/lo split (3 products) ~ fp32 acc.

namespace {

constexpr int Nn = 16384, Cc = 128, Kk = 16;
constexpr int KPAD = 280;
constexpr int ROWB = KPAD * 2;            // 560 B per row
constexpr int TILE_M = 32;
constexpr int NTILES = 131072 / TILE_M;   // 4096
constexpr int WT_HALF = 128 * ROWB;       // 71680 (hi); lo follows
constexpr int U_HALF  = TILE_M * ROWB;    // 17920
constexpr int U_BUF   = 2 * U_HALF;       // 35840
constexpr int SM_WT   = 0;
constexpr int SM_U    = 2 * WT_HALF;      // 143360
constexpr int SM_TOTAL = SM_U + 2 * U_BUF;  // 215040

__device__ __nv_bfloat16 g_wt[2 * WT_HALF / 2];

__device__ __forceinline__ uint32_t smem_u32(const void* p) {
    uint32_t a;
    asm("{ .reg .u64 t; cvta.to.shared.u64 t, %1; cvt.u32.u64 %0, t; }" : "=r"(a) : "l"(p));
    return a;
}
__device__ __forceinline__ uint32_t cvt2bf(float a, float b) {
    uint32_t r;
    asm("cvt.rn.bf16x2.f32 %0, %1, %2;" : "=r"(r) : "f"(b), "f"(a));
    return r;
}
__device__ __forceinline__ uint32_t lo_pack(float a, float b, uint32_t h) {
    float la = a - __uint_as_float(h << 16);
    float lb = b - __uint_as_float(h & 0xffff0000u);
    return cvt2bf(la, lb);
}
__device__ __forceinline__ void sts64(uint32_t addr, uint32_t a, uint32_t b) {
    asm volatile("st.shared.v2.b32 [%0], {%1,%2};" :: "r"(addr), "r"(a), "r"(b) : "memory");
}
__device__ __forceinline__ void ldsm_x4(uint32_t addr, uint32_t* r) {
    asm volatile("ldmatrix.sync.aligned.m8n8.x4.shared.b16 {%0,%1,%2,%3}, [%4];"
                 : "=r"(r[0]), "=r"(r[1]), "=r"(r[2]), "=r"(r[3]) : "r"(addr));
}
__device__ __forceinline__ void mma_bf16(float* c, const uint32_t* a,
                                         uint32_t b0, uint32_t b1) {
    asm volatile(
        "mma.sync.aligned.m16n8k16.row.col.f32.bf16.bf16.f32 "
        "{%0,%1,%2,%3}, {%4,%5,%6,%7}, {%8,%9}, {%0,%1,%2,%3};"
        : "+f"(c[0]), "+f"(c[1]), "+f"(c[2]), "+f"(c[3])
        : "r"(a[0]), "r"(a[1]), "r"(a[2]), "r"(a[3]), "r"(b0), "r"(b1));
}

__global__ void prepack(const float* __restrict__ ws, const float* __restrict__ we) {
    int t = blockIdx.x * blockDim.x + threadIdx.x;
    if (t >= 128 * KPAD) return;
    int n = t / KPAD, k = t % KPAD;
    float w = 0.f;
    if (k < 128) w = ws[k * 128 + n];
    else if (k < 260) w = we[(k - 128) * 128 + n];
    __nv_bfloat16 hi = __float2bfloat16_rn(w);
    __nv_bfloat16 lo = __float2bfloat16_rn(w - __bfloat162float(hi));
    g_wt[n * KPAD + k] = hi;
    g_wt[WT_HALF / 2 + n * KPAD + k] = lo;
}

__global__ __launch_bounds__(512, 1) void geconv(
    const float* __restrict__ x, const float* __restrict__ pos,
    const int* __restrict__ idx, float* __restrict__ out)
{
    extern __shared__ __align__(16) char smem[];
    const uint32_t smb = smem_u32(smem);
    const int tid = threadIdx.x, wid = tid >> 5, lane = tid & 31;

    // stage weights (hi+lo) into smem once
    {
        const int4* src = (const int4*)g_wt;
        int4* dst = (int4*)(smem + SM_WT);
        for (int i = tid; i < 2 * WT_HALF / 16; i += 512) dst[i] = src[i];
    }
    // zero the constant pad region k[260..280) of both U buffers, once
    for (int i = tid; i < 128 * 10; i += 512) {
        int row = i / 10, w = i % 10;
        int buf = row >> 6, rem = row & 63, hl = rem >> 5, r = rem & 31;
        uint32_t a = smb + SM_U + (uint32_t)buf * U_BUF + (uint32_t)hl * U_HALF
                   + (uint32_t)r * ROWB + 520 + 4 * w;
        asm volatile("st.shared.b32 [%0], %1;" :: "r"(a), "r"(0u) : "memory");
    }
    __syncthreads();

    const float inv = 1.0f / 16.0f;
    const int grid = gridDim.x;
    const int n_t = (NTILES - (int)blockIdx.x + grid - 1) / grid;

    // ldmatrix per-thread offsets
    const int g8 = lane >> 3, r8 = lane & 7;
    const uint32_t a_off = (uint32_t)(((g8 & 1) * 8 + r8) * ROWB + (g8 >> 1) * 16);
    const uint32_t b_base =
        (uint32_t)((16 * wid + (g8 >> 1) * 8 + r8) * ROWB + (g8 & 1) * 16);

    for (int it = 0; it <= n_t; ++it) {
        if (wid >= 8) {
            // ========================= gather warps =========================
            if (it < n_t) {
                const int tile = blockIdx.x + it * grid;
                const int tile_p0 = tile * TILE_M;
                const int b = tile_p0 >> 14;
                const float* xb = x + (size_t)b * Nn * Cc;
                const float* pb = pos + (size_t)b * Nn * 3;
                const uint32_t ub = smb + SM_U + (uint32_t)(it & 1) * U_BUF;
                const int gw = wid - 8;
                const int m0 = gw * 4;
                const int p0 = tile_p0 + m0;
                const int l16 = lane & 15, half = lane >> 4;

                // idx for 4 points (half-warp per point within a pair)
                int idxA = __ldg(idx + (size_t)(p0 + half) * Kk + l16);
                int idxB = __ldg(idx + (size_t)(p0 + 2 + half) * Kk + l16);

                // ---- neighbor sums, 4 points interleaved ----
                float4 s[4];
                #pragma unroll
                for (int q = 0; q < 4; ++q) s[q] = make_float4(0.f, 0.f, 0.f, 0.f);
                #pragma unroll
                for (int k = 0; k < Kk; ++k) {
                    int jA0 = __shfl_sync(0xffffffffu, idxA, k);
                    int jA1 = __shfl_sync(0xffffffffu, idxA, 16 + k);
                    int jB0 = __shfl_sync(0xffffffffu, idxB, k);
                    int jB1 = __shfl_sync(0xffffffffu, idxB, 16 + k);
                    float4 v0 = ((const float4*)(xb + (size_t)jA0 * Cc))[lane];
                    float4 v1 = ((const float4*)(xb + (size_t)jA1 * Cc))[lane];
                    float4 v2 = ((const float4*)(xb + (size_t)jB0 * Cc))[lane];
                    float4 v3 = ((const float4*)(xb + (size_t)jB1 * Cc))[lane];
                    s[0].x += v0.x; s[0].y += v0.y; s[0].z += v0.z; s[0].w += v0.w;
                    s[1].x += v1.x; s[1].y += v1.y; s[1].z += v1.z; s[1].w += v1.w;
                    s[2].x += v2.x; s[2].y += v2.y; s[2].z += v2.z; s[2].w += v2.w;
                    s[3].x += v3.x; s[3].y += v3.y; s[3].z += v3.z; s[3].w += v3.w;
                }
                #pragma unroll
                for (int q = 0; q < 4; ++q) {
                    const uint32_t rq = ub + (uint32_t)(m0 + q) * ROWB;
                    float sx = s[q].x * inv, sy = s[q].y * inv;
                    float sz = s[q].z * inv, sw = s[q].w * inv;
                    uint32_t g0 = cvt2bf(sx, sy), g1 = cvt2bf(sz, sw);
                    sts64(rq + 256 + 8 * lane, g0, g1);
                    sts64(rq + U_HALF + 256 + 8 * lane,
                          lo_pack(sx, sy, g0), lo_pack(sz, sw, g1));
                }

                // ---- self features ----
                #pragma unroll
                for (int q = 0; q < 4; ++q) {
                    const int n = (p0 + q) & (Nn - 1);
                    const uint32_t rq = ub + (uint32_t)(m0 + q) * ROWB;
                    float4 xi = ((const float4*)(xb + (size_t)n * Cc))[lane];
                    uint32_t h0 = cvt2bf(xi.x, xi.y), h1 = cvt2bf(xi.z, xi.w);
                    sts64(rq + 8 * lane, h0, h1);
                    sts64(rq + U_HALF + 8 * lane,
                          lo_pack(xi.x, xi.y, h0), lo_pack(xi.z, xi.w, h1));
                }

                // ---- pos tails (pairs; half-warp per point, reduce over 16) ----
                #pragma unroll
                for (int pr = 0; pr < 2; ++pr) {
                    const int p = p0 + 2 * pr + half;
                    const int n = p & (Nn - 1);
                    const int myi = pr ? idxB : idxA;
                    float pi0 = pb[n * 3], pi1 = pb[n * 3 + 1], pi2 = pb[n * 3 + 2];
                    const float* pj = pb + (size_t)myi * 3;
                    float r0 = pi0 - pj[0], r1 = pi1 - pj[1], r2 = pi2 - pj[2];
                    float ds = r0 * r0 + r1 * r1 + r2 * r2;
                    #pragma unroll
                    for (int o = 8; o >= 1; o >>= 1) {
                        r0 += __shfl_xor_sync(0xffffffffu, r0, o);
                        r1 += __shfl_xor_sync(0xffffffffu, r1, o);
                        r2 += __shfl_xor_sync(0xffffffffu, r2, o);
                        ds += __shfl_xor_sync(0xffffffffu, ds, o);
                    }
                    if (l16 == 0) {
                        r0 *= inv; r1 *= inv; r2 *= inv; ds *= inv;
                        uint32_t t0 = cvt2bf(r0, r1), t1 = cvt2bf(r2, ds);
                        const uint32_t rq = ub + (uint32_t)(m0 + 2 * pr + half) * ROWB;
                        sts64(rq + 512, t0, t1);
                        sts64(rq + U_HALF + 512,
                              lo_pack(r0, r1, t0), lo_pack(r2, ds, t1));
                    }
                }
            }
        } else {
            // ========================= mma warps =========================
            if (it >= 1) {
                const int tile = blockIdx.x + (it - 1) * grid;
                const uint32_t ub_hi = smb + SM_U + (uint32_t)((it - 1) & 1) * U_BUF;
                const uint32_t ub_lo = ub_hi + U_HALF;
                const uint32_t wt_hi = smb + SM_WT + b_base;
                const uint32_t wt_lo = wt_hi + WT_HALF;

                float c[2][2][4];
                #pragma unroll
                for (int mt = 0; mt < 2; ++mt)
                    #pragma unroll
                    for (int nt = 0; nt < 2; ++nt)
                        #pragma unroll
                        for (int q = 0; q < 4; ++q) c[mt][nt][q] = 0.f;

                #pragma unroll 1
                for (int kt = 0; kt < 17; ++kt) {
                    uint32_t bh[4], bl[4];
                    ldsm_x4(wt_hi + kt * 32, bh);
                    ldsm_x4(wt_lo + kt * 32, bl);
                    #pragma unroll
                    for (int mt = 0; mt < 2; ++mt) {
                        uint32_t ah[4], al[4];
                        ldsm_x4(ub_hi + (uint32_t)(mt * 16) * ROWB + kt * 32 + a_off, ah);
                        ldsm_x4(ub_lo + (uint32_t)(mt * 16) * ROWB + kt * 32 + a_off, al);
                        mma_bf16(c[mt][0], ah, bh[0], bh[1]);
                        mma_bf16(c[mt][1], ah, bh[2], bh[3]);
                        mma_bf16(c[mt][0], al, bh[0], bh[1]);
                        mma_bf16(c[mt][1], al, bh[2], bh[3]);
                        mma_bf16(c[mt][0], ah, bl[0], bl[1]);
                        mma_bf16(c[mt][1], ah, bl[2], bl[3]);
                    }
                }

                const int tile_p0 = tile * TILE_M;
                #pragma unroll
                for (int mt = 0; mt < 2; ++mt) {
                    #pragma unroll
                    for (int nt = 0; nt < 2; ++nt) {
                        const int m0r = mt * 16 + (lane >> 2);
                        const int nc = 16 * wid + nt * 8 + 2 * (lane & 3);
                        float* o0 = out + (size_t)(tile_p0 + m0r) * 128 + nc;
                        float* o1 = out + (size_t)(tile_p0 + m0r + 8) * 128 + nc;
                        float v0 = c[mt][nt][0], v1 = c[mt][nt][1];
                        float v2 = c[mt][nt][2], v3 = c[mt][nt][3];
                        float2 w0, w1;
                        w0.x = v0 > 0.f ? v0 : 0.2f * v0;
                        w0.y = v1 > 0.f ? v1 : 0.2f * v1;
                        w1.x = v2 > 0.f ? v2 : 0.2f * v2;
                        w1.y = v3 > 0.f ? v3 : 0.2f * v3;
                        *(float2*)o0 = w0;
                        *(float2*)o1 = w1;
                    }
                }
            }
        }
        __syncthreads();
    }
}

}  // namespace

extern "C" void kernel_launch(void* const* d_in, const int* in_sizes, int n_in,
                              void* d_out, int out_size) {
    const float* x   = (const float*)d_in[0];   // [8,16384,128]
    const float* pos = (const float*)d_in[1];   // [8,16384,3]
    const int*   idx = (const int*)d_in[2];     // [8,16384,16]
    const float* ws  = (const float*)d_in[3];   // [128,128]
    const float* we  = (const float*)d_in[4];   // [132,128]
    float* out = (float*)d_out;

    cudaFuncSetAttribute(geconv, cudaFuncAttributeMaxDynamicSharedMemorySize, SM_TOTAL);
    prepack<<<140, 256>>>(ws, we);
    geconv<<<148, 512, SM_TOTAL>>>(x, pos, idx, out);
}

// round 6
// speedup vs baseline: 4.5803x; 1.2283x over previous
#include <cuda_runtime.h>
#include <cuda_fp16.h>
#include <cstdint>

// GeometricEdgeConv v3: warp-specialized gather + mma.sync fp16 GEMM.
// A (gathered u rows) split fp16 hi+lo (2 products); W single fp16
// (rel err ~1.5e-4 << 1e-3 gate). TILE_M=64, weights 71.7KB resident,
// u double-buffered. 768 threads: 8 mma warps (m32 x n32 each) +
// 16 gather warps (4 points each, 4-way interleaved neighbor loads).

namespace {

constexpr int Nn = 16384, Cc = 128, Kk = 16;
constexpr int KPAD = 280;
constexpr int ROWB = KPAD * 2;             // 560 B row (35x16B: LDSM conflict-free)
constexpr int TILE_M = 64;
constexpr int NTILES = 131072 / TILE_M;    // 2048
constexpr int WT_BYTES = 128 * ROWB;       // 71680 (fp16 single)
constexpr int U_HALF  = TILE_M * ROWB;     // 35840 (hi); lo follows
constexpr int U_BUF   = 2 * U_HALF;        // 71680
constexpr int SM_WT   = 0;
constexpr int SM_U    = WT_BYTES;          // 71680
constexpr int SM_TOTAL = SM_U + 2 * U_BUF; // 215040

__device__ __half g_wt[WT_BYTES / 2];      // W^T [n=128][k=280] fp16

__device__ __forceinline__ uint32_t smem_u32(const void* p) {
    uint32_t a;
    asm("{ .reg .u64 t; cvta.to.shared.u64 t, %1; cvt.u32.u64 %0, t; }" : "=r"(a) : "l"(p));
    return a;
}
// pack: low half = a, high half = b
__device__ __forceinline__ uint32_t cvt2h(float a, float b) {
    uint32_t r;
    asm("cvt.rn.f16x2.f32 %0, %1, %2;" : "=r"(r) : "f"(b), "f"(a));
    return r;
}
__device__ __forceinline__ uint32_t lo_pack(float a, float b, uint32_t h) {
    __half2 hh = *reinterpret_cast<__half2*>(&h);
    float la = a - __half2float(hh.x);
    float lb = b - __half2float(hh.y);
    return cvt2h(la, lb);
}
__device__ __forceinline__ void sts64(uint32_t addr, uint32_t a, uint32_t b) {
    asm volatile("st.shared.v2.b32 [%0], {%1,%2};" :: "r"(addr), "r"(a), "r"(b) : "memory");
}
__device__ __forceinline__ void ldsm_x4(uint32_t addr, uint32_t* r) {
    asm volatile("ldmatrix.sync.aligned.m8n8.x4.shared.b16 {%0,%1,%2,%3}, [%4];"
                 : "=r"(r[0]), "=r"(r[1]), "=r"(r[2]), "=r"(r[3]) : "r"(addr));
}
__device__ __forceinline__ void mma_f16(float* c, const uint32_t* a,
                                        uint32_t b0, uint32_t b1) {
    asm volatile(
        "mma.sync.aligned.m16n8k16.row.col.f32.f16.f16.f32 "
        "{%0,%1,%2,%3}, {%4,%5,%6,%7}, {%8,%9}, {%0,%1,%2,%3};"
        : "+f"(c[0]), "+f"(c[1]), "+f"(c[2]), "+f"(c[3])
        : "r"(a[0]), "r"(a[1]), "r"(a[2]), "r"(a[3]), "r"(b0), "r"(b1));
}

__global__ void prepack(const float* __restrict__ ws, const float* __restrict__ we) {
    int t = blockIdx.x * blockDim.x + threadIdx.x;
    if (t >= 128 * KPAD) return;
    int n = t / KPAD, k = t % KPAD;
    float w = 0.f;
    if (k < 128) w = ws[k * 128 + n];
    else if (k < 260) w = we[(k - 128) * 128 + n];
    g_wt[n * KPAD + k] = __float2half_rn(w);
}

__global__ __launch_bounds__(768, 1) void geconv(
    const float* __restrict__ x, const float* __restrict__ pos,
    const int* __restrict__ idx, float* __restrict__ out)
{
    extern __shared__ __align__(16) char smem[];
    const uint32_t smb = smem_u32(smem);
    const int tid = threadIdx.x, wid = tid >> 5, lane = tid & 31;

    // stage weights into smem once
    {
        const int4* src = (const int4*)g_wt;
        int4* dst = (int4*)(smem + SM_WT);
        for (int i = tid; i < WT_BYTES / 16; i += 768) dst[i] = src[i];
    }
    // zero constant pad k[260..280) of both U buffers (hi and lo), once
    for (int i = tid; i < 256 * 10; i += 768) {
        int row = i / 10, w = i % 10;           // row in [0,256): buf*128 + half*64 + r
        int buf = row >> 7, rem = row & 127, hl = rem >> 6, r = rem & 63;
        uint32_t a = smb + SM_U + (uint32_t)buf * U_BUF + (uint32_t)hl * U_HALF
                   + (uint32_t)r * ROWB + 520 + 4 * w;
        asm volatile("st.shared.b32 [%0], %1;" :: "r"(a), "r"(0u) : "memory");
    }
    __syncthreads();

    const float inv = 1.0f / 16.0f;
    const int grid = gridDim.x;
    const int n_t = (NTILES - (int)blockIdx.x + grid - 1) / grid;

    // ldmatrix per-thread offsets
    const int g8 = lane >> 3, r8 = lane & 7;
    const uint32_t a_off = (uint32_t)(((g8 & 1) * 8 + r8) * ROWB + (g8 >> 1) * 16);
    const int mg = (wid >> 2) & 1;               // mma m-group (rows mg*32)
    const int cg = wid & 3;                      // mma col-group (cols cg*32)
    const uint32_t b_off =
        (uint32_t)((32 * cg + (g8 >> 1) * 8 + r8) * ROWB + (g8 & 1) * 16);

    for (int it = 0; it <= n_t; ++it) {
        if (wid >= 8) {
            // ========================= gather warps (16) =========================
            if (it < n_t) {
                const int tile = blockIdx.x + it * grid;
                const int tile_p0 = tile * TILE_M;
                const int b = tile_p0 >> 14;
                const float* xb = x + (size_t)b * Nn * Cc;
                const float* pb = pos + (size_t)b * Nn * 3;
                const uint32_t ub = smb + SM_U + (uint32_t)(it & 1) * U_BUF;
                const int gw = wid - 8;
                const int m0 = gw * 4;
                const int p0 = tile_p0 + m0;
                const int l16 = lane & 15, half = lane >> 4;

                int idxA = __ldg(idx + (size_t)(p0 + half) * Kk + l16);
                int idxB = __ldg(idx + (size_t)(p0 + 2 + half) * Kk + l16);

                // neighbor sums, 4 points interleaved
                float4 s[4];
                #pragma unroll
                for (int q = 0; q < 4; ++q) s[q] = make_float4(0.f, 0.f, 0.f, 0.f);
                #pragma unroll
                for (int k = 0; k < Kk; ++k) {
                    int jA0 = __shfl_sync(0xffffffffu, idxA, k);
                    int jA1 = __shfl_sync(0xffffffffu, idxA, 16 + k);
                    int jB0 = __shfl_sync(0xffffffffu, idxB, k);
                    int jB1 = __shfl_sync(0xffffffffu, idxB, 16 + k);
                    float4 v0 = ((const float4*)(xb + (size_t)jA0 * Cc))[lane];
                    float4 v1 = ((const float4*)(xb + (size_t)jA1 * Cc))[lane];
                    float4 v2 = ((const float4*)(xb + (size_t)jB0 * Cc))[lane];
                    float4 v3 = ((const float4*)(xb + (size_t)jB1 * Cc))[lane];
                    s[0].x += v0.x; s[0].y += v0.y; s[0].z += v0.z; s[0].w += v0.w;
                    s[1].x += v1.x; s[1].y += v1.y; s[1].z += v1.z; s[1].w += v1.w;
                    s[2].x += v2.x; s[2].y += v2.y; s[2].z += v2.z; s[2].w += v2.w;
                    s[3].x += v3.x; s[3].y += v3.y; s[3].z += v3.z; s[3].w += v3.w;
                }
                #pragma unroll
                for (int q = 0; q < 4; ++q) {
                    const uint32_t rq = ub + (uint32_t)(m0 + q) * ROWB;
                    float sx = s[q].x * inv, sy = s[q].y * inv;
                    float sz = s[q].z * inv, sw = s[q].w * inv;
                    uint32_t g0 = cvt2h(sx, sy), g1 = cvt2h(sz, sw);
                    sts64(rq + 256 + 8 * lane, g0, g1);
                    sts64(rq + U_HALF + 256 + 8 * lane,
                          lo_pack(sx, sy, g0), lo_pack(sz, sw, g1));
                }

                // self features
                #pragma unroll
                for (int q = 0; q < 4; ++q) {
                    const int n = (p0 + q) & (Nn - 1);
                    const uint32_t rq = ub + (uint32_t)(m0 + q) * ROWB;
                    float4 xi = ((const float4*)(xb + (size_t)n * Cc))[lane];
                    uint32_t h0 = cvt2h(xi.x, xi.y), h1 = cvt2h(xi.z, xi.w);
                    sts64(rq + 8 * lane, h0, h1);
                    sts64(rq + U_HALF + 8 * lane,
                          lo_pack(xi.x, xi.y, h0), lo_pack(xi.z, xi.w, h1));
                }

                // pos tails (half-warp per point of a pair)
                #pragma unroll
                for (int pr = 0; pr < 2; ++pr) {
                    const int p = p0 + 2 * pr + half;
                    const int n = p & (Nn - 1);
                    const int myi = pr ? idxB : idxA;
                    float pi0 = pb[n * 3], pi1 = pb[n * 3 + 1], pi2 = pb[n * 3 + 2];
                    const float* pj = pb + (size_t)myi * 3;
                    float r0 = pi0 - pj[0], r1 = pi1 - pj[1], r2 = pi2 - pj[2];
                    float ds = r0 * r0 + r1 * r1 + r2 * r2;
                    #pragma unroll
                    for (int o = 8; o >= 1; o >>= 1) {
                        r0 += __shfl_xor_sync(0xffffffffu, r0, o);
                        r1 += __shfl_xor_sync(0xffffffffu, r1, o);
                        r2 += __shfl_xor_sync(0xffffffffu, r2, o);
                        ds += __shfl_xor_sync(0xffffffffu, ds, o);
                    }
                    if (l16 == 0) {
                        r0 *= inv; r1 *= inv; r2 *= inv; ds *= inv;
                        uint32_t t0 = cvt2h(r0, r1), t1 = cvt2h(r2, ds);
                        const uint32_t rq = ub + (uint32_t)(m0 + 2 * pr + half) * ROWB;
                        sts64(rq + 512, t0, t1);
                        sts64(rq + U_HALF + 512,
                              lo_pack(r0, r1, t0), lo_pack(r2, ds, t1));
                    }
                }
            }
        } else {
            // ========================= mma warps (8: 2 m-groups x 4 col-groups) ==
            if (it >= 1) {
                const int tile = blockIdx.x + (it - 1) * grid;
                const uint32_t ub_hi = smb + SM_U + (uint32_t)((it - 1) & 1) * U_BUF
                                     + (uint32_t)(mg * 32) * ROWB;
                const uint32_t ub_lo = ub_hi + U_HALF;
                const uint32_t wt = smb + SM_WT + b_off;

                float c[2][4][4];
                #pragma unroll
                for (int mt = 0; mt < 2; ++mt)
                    #pragma unroll
                    for (int nt = 0; nt < 4; ++nt)
                        #pragma unroll
                        for (int q = 0; q < 4; ++q) c[mt][nt][q] = 0.f;

                #pragma unroll 1
                for (int kt = 0; kt < 17; ++kt) {
                    uint32_t b0[4], b1[4];            // cols cg*32 .. +31
                    ldsm_x4(wt + kt * 32, b0);
                    ldsm_x4(wt + kt * 32 + 16 * ROWB, b1);
                    #pragma unroll
                    for (int mt = 0; mt < 2; ++mt) {
                        uint32_t ah[4], al[4];
                        ldsm_x4(ub_hi + (uint32_t)(mt * 16) * ROWB + kt * 32 + a_off, ah);
                        ldsm_x4(ub_lo + (uint32_t)(mt * 16) * ROWB + kt * 32 + a_off, al);
                        mma_f16(c[mt][0], ah, b0[0], b0[1]);
                        mma_f16(c[mt][1], ah, b0[2], b0[3]);
                        mma_f16(c[mt][2], ah, b1[0], b1[1]);
                        mma_f16(c[mt][3], ah, b1[2], b1[3]);
                        mma_f16(c[mt][0], al, b0[0], b0[1]);
                        mma_f16(c[mt][1], al, b0[2], b0[3]);
                        mma_f16(c[mt][2], al, b1[0], b1[1]);
                        mma_f16(c[mt][3], al, b1[2], b1[3]);
                    }
                }

                const int tile_p0 = tile * TILE_M + mg * 32;
                #pragma unroll
                for (int mt = 0; mt < 2; ++mt) {
                    #pragma unroll
                    for (int nt = 0; nt < 4; ++nt) {
                        const int m0r = mt * 16 + (lane >> 2);
                        const int nc = 32 * cg + nt * 8 + 2 * (lane & 3);
                        float* o0 = out + (size_t)(tile_p0 + m0r) * 128 + nc;
                        float* o1 = out + (size_t)(tile_p0 + m0r + 8) * 128 + nc;
                        float v0 = c[mt][nt][0], v1 = c[mt][nt][1];
                        float v2 = c[mt][nt][2], v3 = c[mt][nt][3];
                        float2 w0, w1;
                        w0.x = v0 > 0.f ? v0 : 0.2f * v0;
                        w0.y = v1 > 0.f ? v1 : 0.2f * v1;
                        w1.x = v2 > 0.f ? v2 : 0.2f * v2;
                        w1.y = v3 > 0.f ? v3 : 0.2f * v3;
                        *(float2*)o0 = w0;
                        *(float2*)o1 = w1;
                    }
                }
            }
        }
        __syncthreads();
    }
}

}  // namespace

extern "C" void kernel_launch(void* const* d_in, const int* in_sizes, int n_in,
                              void* d_out, int out_size) {
    const float* x   = (const float*)d_in[0];   // [8,16384,128]
    const float* pos = (const float*)d_in[1];   // [8,16384,3]
    const int*   idx = (const int*)d_in[2];     // [8,16384,16]
    const float* ws  = (const float*)d_in[3];   // [128,128]
    const float* we  = (const float*)d_in[4];   // [132,128]
    float* out = (float*)d_out;

    cudaFuncSetAttribute(geconv, cudaFuncAttributeMaxDynamicSharedMemorySize, SM_TOTAL);
    prepack<<<140, 256>>>(ws, we);
    geconv<<<148, 768, SM_TOTAL>>>(x, pos, idx, out);
}

// round 7
// speedup vs baseline: 5.5123x; 1.2035x over previous
#include <cuda_runtime.h>
#include <cuda_fp16.h>
#include <cstdint>

// GeometricEdgeConv v4: 3-kernel pipeline.
//  1) prepack: W2^T = [Ws | We_feat]^T -> fp16 [256][136] (padded, LDSM-ready)
//  2) prepass: y[131072][256] fp16 = x @ W2   (HMMA fp16, persistent tiles)
//  3) gather:  out[p] = leaky( y_self[p] + mean_k y_edge[idx] + pos-GEMV )
// The edge linear commutes past the mean, AND past the gather itself:
// precomputing y turns the expensive fused gather+GEMM into a pure fp16
// row-average (half the gather bytes, zero LDSM restreaming).

namespace {

constexpr int Nn = 16384;

// prepass smem layout
constexpr int KH = 136;                    // 128 k + 8 pad (halves)
constexpr int RB = KH * 2;                 // 272 B row stride (LDSM conflict-free)
constexpr int SM_B2 = 0;                   // W2^T: 256 rows -> 69632 B
constexpr int SM_A2 = 256 * RB;            // x tile fp16: 128 rows -> 34816 B
constexpr int SM_Y  = SM_A2 + 128 * RB;    // ybuf: 128 x 264 halves
constexpr int YSTR  = 264;                 // halves (528 B rows)
constexpr int SM2_TOTAL = SM_Y + 128 * YSTR * 2;   // 172032

__device__ __half g_wt2[256 * KH];
__device__ __half g_y[(size_t)131072 * 256];       // 64 MB scratch

__device__ __forceinline__ uint32_t smem_u32(const void* p) {
    uint32_t a;
    asm("{ .reg .u64 t; cvta.to.shared.u64 t, %1; cvt.u32.u64 %0, t; }" : "=r"(a) : "l"(p));
    return a;
}
// pack: low half = a, high half = b
__device__ __forceinline__ uint32_t cvt2h(float a, float b) {
    uint32_t r;
    asm("cvt.rn.f16x2.f32 %0, %1, %2;" : "=r"(r) : "f"(b), "f"(a));
    return r;
}
__device__ __forceinline__ void sts32(uint32_t addr, uint32_t v) {
    asm volatile("st.shared.b32 [%0], %1;" :: "r"(addr), "r"(v) : "memory");
}
__device__ __forceinline__ void sts64(uint32_t addr, uint32_t a, uint32_t b) {
    asm volatile("st.shared.v2.b32 [%0], {%1,%2};" :: "r"(addr), "r"(a), "r"(b) : "memory");
}
__device__ __forceinline__ void lds128(uint32_t addr, uint32_t* r) {
    asm volatile("ld.shared.v4.b32 {%0,%1,%2,%3}, [%4];"
                 : "=r"(r[0]), "=r"(r[1]), "=r"(r[2]), "=r"(r[3]) : "r"(addr));
}
__device__ __forceinline__ void ldsm_x4(uint32_t addr, uint32_t* r) {
    asm volatile("ldmatrix.sync.aligned.m8n8.x4.shared.b16 {%0,%1,%2,%3}, [%4];"
                 : "=r"(r[0]), "=r"(r[1]), "=r"(r[2]), "=r"(r[3]) : "r"(addr));
}
__device__ __forceinline__ void mma_f16(float* c, const uint32_t* a,
                                        uint32_t b0, uint32_t b1) {
    asm volatile(
        "mma.sync.aligned.m16n8k16.row.col.f32.f16.f16.f32 "
        "{%0,%1,%2,%3}, {%4,%5,%6,%7}, {%8,%9}, {%0,%1,%2,%3};"
        : "+f"(c[0]), "+f"(c[1]), "+f"(c[2]), "+f"(c[3])
        : "r"(a[0]), "r"(a[1]), "r"(a[2]), "r"(a[3]), "r"(b0), "r"(b1));
}

// ---------------------------------------------------------------- prepack
__global__ void prepack(const float* __restrict__ ws, const float* __restrict__ we) {
    int t = blockIdx.x * 256 + threadIdx.x;
    if (t >= 256 * KH) return;
    int n = t / KH, k = t % KH;
    float v = 0.f;
    if (k < 128) v = (n < 128) ? ws[k * 128 + n] : we[k * 128 + (n - 128)];
    g_wt2[t] = __float2half_rn(v);
}

// ---------------------------------------------------------------- prepass GEMM
// y[131072][256] = x[131072][128] @ W2[128][256], fp16 in/out, fp32 accum.
__global__ __launch_bounds__(512, 1) void prepass(const float* __restrict__ x) {
    extern __shared__ __align__(16) char sm[];
    const uint32_t smb = smem_u32(sm);
    const int tid = threadIdx.x, wid = tid >> 5, lane = tid & 31;

    // stage W2^T once
    {
        const int4* s = (const int4*)g_wt2;
        int4* d = (int4*)(sm + SM_B2);
        for (int i = tid; i < 256 * RB / 16; i += 512) d[i] = s[i];
    }
    __syncthreads();

    const int g8 = lane >> 3, r8 = lane & 7;
    const uint32_t a_off = (uint32_t)(((g8 & 1) * 8 + r8) * RB + (g8 >> 1) * 16);
    const uint32_t b_off = (uint32_t)(((g8 >> 1) * 8 + r8) * RB + (g8 & 1) * 16);
    const int mg = wid >> 2, ng = wid & 3;       // warp tile: m32 (mg) x n64 (ng)

    for (int tile = blockIdx.x; tile < 1024; tile += gridDim.x) {
        const int tp0 = tile * 128;

        // load x tile fp32 -> fp16 smem
        #pragma unroll
        for (int it = 0; it < 8; ++it) {
            int j = tid + it * 512;
            int row = j >> 5, c4 = j & 31;
            float4 f = *(const float4*)(x + (size_t)(tp0 + row) * 128 + c4 * 4);
            sts64(smb + SM_A2 + row * RB + c4 * 8, cvt2h(f.x, f.y), cvt2h(f.z, f.w));
        }
        __syncthreads();

        float c[2][8][4];
        #pragma unroll
        for (int mt = 0; mt < 2; ++mt)
            #pragma unroll
            for (int nt = 0; nt < 8; ++nt)
                #pragma unroll
                for (int q = 0; q < 4; ++q) c[mt][nt][q] = 0.f;

        const uint32_t Ab = smb + SM_A2 + (uint32_t)(mg * 32) * RB + a_off;
        const uint32_t Bb = smb + SM_B2 + (uint32_t)(ng * 64) * RB + b_off;
        #pragma unroll
        for (int kt = 0; kt < 8; ++kt) {
            uint32_t af[2][4], bf[4][4];
            ldsm_x4(Ab + kt * 32, af[0]);
            ldsm_x4(Ab + 16 * RB + kt * 32, af[1]);
            #pragma unroll
            for (int nn = 0; nn < 4; ++nn)
                ldsm_x4(Bb + (uint32_t)(nn * 16) * RB + kt * 32, bf[nn]);
            #pragma unroll
            for (int mt = 0; mt < 2; ++mt)
                #pragma unroll
                for (int nn = 0; nn < 4; ++nn) {
                    mma_f16(c[mt][nn * 2],     af[mt], bf[nn][0], bf[nn][1]);
                    mma_f16(c[mt][nn * 2 + 1], af[mt], bf[nn][2], bf[nn][3]);
                }
        }

        // frags -> ybuf (fp16), conflict-free STS
        #pragma unroll
        for (int mt = 0; mt < 2; ++mt)
            #pragma unroll
            for (int nt = 0; nt < 8; ++nt) {
                int row = mg * 32 + mt * 16 + (lane >> 2);
                int col = ng * 64 + nt * 8 + 2 * (lane & 3);
                uint32_t ad = smb + SM_Y + (uint32_t)row * (YSTR * 2) + col * 2;
                sts32(ad, cvt2h(c[mt][nt][0], c[mt][nt][1]));
                sts32(ad + 8 * (YSTR * 2), cvt2h(c[mt][nt][2], c[mt][nt][3]));
            }
        __syncthreads();

        // coalesced 64KB store to g_y
        char* yt = (char*)(g_y + (size_t)tp0 * 256);
        #pragma unroll
        for (int it = 0; it < 8; ++it) {
            int j = tid + it * 512;
            int row = j >> 5, c16 = j & 31;
            uint32_t u[4];
            lds128(smb + SM_Y + (uint32_t)row * (YSTR * 2) + c16 * 16, u);
            *(uint4*)(yt + (size_t)row * 512 + c16 * 16) =
                make_uint4(u[0], u[1], u[2], u[3]);
        }
        __syncthreads();
    }
}

// ---------------------------------------------------------------- gather
__global__ __launch_bounds__(256) void gather(
    const float* __restrict__ pos, const int* __restrict__ idx,
    const float* __restrict__ we, float* __restrict__ out)
{
    __shared__ __align__(16) float wpos[512];    // We rows 128..131 (contiguous)
    const int tid = threadIdx.x;
    wpos[tid] = we[128 * 128 + tid];
    wpos[256 + tid] = we[128 * 128 + 256 + tid];
    __syncthreads();

    const int warp = tid >> 5, lane = tid & 31;
    const int p = blockIdx.x * 8 + warp;
    const int b = p >> 14;
    const int n = p & (Nn - 1);
    const __half* yb = g_y + ((size_t)b << 14) * 256;

    // self: y[p][4l..4l+3]
    uint2 vs = *(const uint2*)(g_y + (size_t)p * 256 + 4 * lane);

    int my = 0;
    if (lane < 16) my = __ldg(idx + (size_t)p * 16 + lane);

    // mean of 16 y_edge rows (fp16 -> fp32 accumulate)
    float4 acc = make_float4(0.f, 0.f, 0.f, 0.f);
    #pragma unroll
    for (int k = 0; k < 16; ++k) {
        int j = __shfl_sync(0xffffffffu, my, k);
        uint2 v = *(const uint2*)(yb + (size_t)j * 256 + 128 + 4 * lane);
        float2 f0 = __half22float2(*(__half2*)&v.x);
        float2 f1 = __half22float2(*(__half2*)&v.y);
        acc.x += f0.x; acc.y += f0.y; acc.z += f1.x; acc.w += f1.y;
    }
    const float inv = 1.0f / 16.0f;

    // pos tail (fp32 exact)
    const float* pb = pos + (size_t)b * Nn * 3;
    float r0 = 0.f, r1 = 0.f, r2 = 0.f, ds = 0.f;
    if (lane < 16) {
        float pi0 = pb[n * 3], pi1 = pb[n * 3 + 1], pi2 = pb[n * 3 + 2];
        const float* pj = pb + (size_t)my * 3;
        r0 = pi0 - pj[0]; r1 = pi1 - pj[1]; r2 = pi2 - pj[2];
        ds = r0 * r0 + r1 * r1 + r2 * r2;
    }
    #pragma unroll
    for (int o = 8; o >= 1; o >>= 1) {
        r0 += __shfl_xor_sync(0xffffffffu, r0, o);
        r1 += __shfl_xor_sync(0xffffffffu, r1, o);
        r2 += __shfl_xor_sync(0xffffffffu, r2, o);
        ds += __shfl_xor_sync(0xffffffffu, ds, o);
    }
    r0 = __shfl_sync(0xffffffffu, r0, 0) * inv;
    r1 = __shfl_sync(0xffffffffu, r1, 0) * inv;
    r2 = __shfl_sync(0xffffffffu, r2, 0) * inv;
    ds = __shfl_sync(0xffffffffu, ds, 0) * inv;

    float2 s0 = __half22float2(*(__half2*)&vs.x);
    float2 s1 = __half22float2(*(__half2*)&vs.y);
    float4 w0 = *(const float4*)(wpos +       4 * lane);
    float4 w1 = *(const float4*)(wpos + 128 + 4 * lane);
    float4 w2 = *(const float4*)(wpos + 256 + 4 * lane);
    float4 w3 = *(const float4*)(wpos + 384 + 4 * lane);

    float v0 = s0.x + acc.x * inv + r0 * w0.x + r1 * w1.x + r2 * w2.x + ds * w3.x;
    float v1 = s0.y + acc.y * inv + r0 * w0.y + r1 * w1.y + r2 * w2.y + ds * w3.y;
    float v2 = s1.x + acc.z * inv + r0 * w0.z + r1 * w1.z + r2 * w2.z + ds * w3.z;
    float v3 = s1.y + acc.w * inv + r0 * w0.w + r1 * w1.w + r2 * w2.w + ds * w3.w;

    float4 r;
    r.x = v0 > 0.f ? v0 : 0.2f * v0;
    r.y = v1 > 0.f ? v1 : 0.2f * v1;
    r.z = v2 > 0.f ? v2 : 0.2f * v2;
    r.w = v3 > 0.f ? v3 : 0.2f * v3;
    *(float4*)(out + (size_t)p * 128 + 4 * lane) = r;
}

}  // namespace

extern "C" void kernel_launch(void* const* d_in, const int* in_sizes, int n_in,
                              void* d_out, int out_size) {
    const float* x   = (const float*)d_in[0];   // [8,16384,128]
    const float* pos = (const float*)d_in[1];   // [8,16384,3]
    const int*   idx = (const int*)d_in[2];     // [8,16384,16]
    const float* ws  = (const float*)d_in[3];   // [128,128]
    const float* we  = (const float*)d_in[4];   // [132,128]
    float* out = (float*)d_out;

    cudaFuncSetAttribute(prepass, cudaFuncAttributeMaxDynamicSharedMemorySize, SM2_TOTAL);
    prepack<<<(256 * KH + 255) / 256, 256>>>(ws, we);
    prepass<<<148, 512, SM2_TOTAL>>>(x);
    gather<<<16384, 256>>>(pos, idx, we, out);
}